// round 2
// baseline (speedup 1.0000x reference)
#include <cuda_runtime.h>
#include <math.h>

#define NN 8000
#define NE 100000
#define NGR 16
#define H 80
#define TW 5
#define TH 400          // TW*H
#define FO 16
#define EPS_BN 1e-5f
#define EPS_LOG 1e-6f

// ---------------- scratch (device globals; no allocation allowed) ----------------
__device__ int   g_deg[NN];
__device__ int   g_fill[NN];
__device__ int   g_off[NN + 1];
__device__ int   g_src[NE];
__device__ float g_amp[NN];
__device__ float g_att[NN];
__device__ float g_delta;
__device__ __align__(16) float g_op[NN * H];
__device__ __align__(16) float g_hi[NN * TH];
__device__ __align__(16) float g_hj[NN * TH];
__device__ __align__(16) float g_agg[NN * 1600];   // [n][t][a*H+h], a in {mean,min,max,std}
__device__ __align__(16) float g_c16[NN * H];      // conv_post output reshaped (N,80)
__device__ __align__(16) float g_lin[NN * H];
__device__ float g_mu[H];
__device__ float g_rstd[H];
__device__ float g_logxc[NN * 40];
__device__ float g_xcf[NN * 40];
__device__ float g_gs[NGR * 40];
__device__ float g_gc[NGR];

// ---------------- setup kernels ----------------
__global__ void k_reset() {
    int i = blockIdx.x * blockDim.x + threadIdx.x;
    if (i < NN) { g_deg[i] = 0; g_fill[i] = 0; }
    if (i < NGR * 40) g_gs[i] = 0.f;
    if (i < NGR) g_gc[i] = 0.f;
    if (i == 0) g_delta = 0.f;
}

__global__ void k_count(const int* __restrict__ ei) {
    int i = blockIdx.x * blockDim.x + threadIdx.x;
    if (i < NE) atomicAdd(&g_deg[ei[NE + i]], 1);
}

__global__ void k_scan() {   // single block, 1024 threads
    __shared__ int sh[1024];
    int tid = threadIdx.x;
    const int per = 8;       // 1024*8 = 8192 >= 8000
    int base = tid * per;
    int s = 0;
    for (int j = 0; j < per; j++) { int idx = base + j; if (idx < NN) s += g_deg[idx]; }
    sh[tid] = s; __syncthreads();
    for (int o = 1; o < 1024; o <<= 1) {
        int v = (tid >= o) ? sh[tid - o] : 0;
        __syncthreads();
        sh[tid] += v;
        __syncthreads();
    }
    int run = (tid == 0) ? 0 : sh[tid - 1];
    for (int j = 0; j < per; j++) {
        int idx = base + j;
        if (idx < NN) { g_off[idx] = run; run += g_deg[idx]; }
    }
    if (tid == 0) g_off[NN] = sh[1023];
}

__global__ void k_scatter(const int* __restrict__ ei) {
    int i = blockIdx.x * blockDim.x + threadIdx.x;
    if (i < NE) {
        int t = ei[NE + i];
        int p = g_off[t] + atomicAdd(&g_fill[t], 1);
        g_src[p] = ei[i];
    }
}

__global__ void k_delta() {  // single block
    __shared__ float sh[1024];
    int tid = threadIdx.x;
    float s = 0.f;
    for (int i = tid; i < NN; i += 1024) s += logf((float)g_deg[i] + 1.f);
    sh[tid] = s; __syncthreads();
    for (int o = 512; o; o >>= 1) { if (tid < o) sh[tid] += sh[tid + o]; __syncthreads(); }
    if (tid == 0) g_delta = sh[0] / (float)NN;
}

__global__ void k_nodeinfo() {
    int i = blockIdx.x * blockDim.x + threadIdx.x;
    if (i < NN) {
        int d = g_deg[i];
        float dc = (float)(d > 1 ? d : 1);
        float L = logf(dc + 1.f);
        float delta = g_delta;
        g_amp[i] = L / delta;
        g_att[i] = delta / L;
    }
}

__global__ void k_op0(const float* __restrict__ x, const float* __restrict__ W,
                      const float* __restrict__ b) {
    int i = blockIdx.x * blockDim.x + threadIdx.x;
    if (i < NN * H) {
        int n = i / H, h = i % H;
        g_op[i] = x[2 * n] * W[h] + b[h];
    }
}

// ---------------- GEMM 1: hi/hj = op @ conv_pre_W (M=8000, K=80, N=800) ----------------
__global__ void k_gemm_pre(const float* __restrict__ W) {   // W: (T, 2H, H) for this layer
    __shared__ __align__(16) float sA[16][64];
    __shared__ __align__(16) float sB[16][64];
    int tx = threadIdx.x, ty = threadIdx.y;
    int tid = ty * 16 + tx;
    int m0 = blockIdx.x * 64;
    int c0 = blockIdx.y * 64;
    float acc[4][4] = {};
    int nl = tid / 4, kq = tid % 4;   // A-staging role
    int cl = tid % 64, kq2 = tid / 64; // B-staging role
    for (int kk = 0; kk < 80; kk += 16) {
        float4 av = *(const float4*)(g_op + (m0 + nl) * H + kk + kq * 4);
        sA[kq * 4 + 0][nl] = av.x; sA[kq * 4 + 1][nl] = av.y;
        sA[kq * 4 + 2][nl] = av.z; sA[kq * 4 + 3][nl] = av.w;
#pragma unroll
        for (int j = 0; j < 4; j++) {
            int k = kq2 * 4 + j;
            int kg = kk + k;
            int c = c0 + cl;
            float val = 0.f;
            if (c < 800) {
                int cc = c < 400 ? c : c - 400;
                int f  = c < 400 ? kg : kg + 80;
                val = W[(cc / H * 160 + f) * H + (cc % H)];
            }
            sB[k][cl] = val;
        }
        __syncthreads();
#pragma unroll
        for (int k = 0; k < 16; k++) {
            float a[4], bv[4];
            *(float4*)a  = *(const float4*)&sA[k][ty * 4];
            *(float4*)bv = *(const float4*)&sB[k][tx * 4];
#pragma unroll
            for (int i = 0; i < 4; i++)
#pragma unroll
                for (int j = 0; j < 4; j++) acc[i][j] += a[i] * bv[j];
        }
        __syncthreads();
    }
#pragma unroll
    for (int i = 0; i < 4; i++) {
        int n = m0 + ty * 4 + i;
#pragma unroll
        for (int j = 0; j < 4; j++) {
            int c = c0 + tx * 4 + j;
            if (c < 800) {
                if (c < 400) g_hi[n * TH + c] = acc[i][j];
                else         g_hj[n * TH + c - 400] = acc[i][j];
            }
        }
    }
}

// ---------------- aggregation: per-node CSR gather of hj[src] ----------------
__global__ void k_agg(const float* __restrict__ preb) {  // preb: (T,H) for this layer
    int v = blockIdx.x;
    int tid = threadIdx.x;  // 128
    float sm[4] = {0, 0, 0, 0}, sq[4] = {0, 0, 0, 0};
    float mn[4], mx[4];
#pragma unroll
    for (int k = 0; k < 4; k++) { mn[k] = 3.4e38f; mx[k] = -3.4e38f; }
    __shared__ int sS[128];
    int beg = g_off[v], end = g_off[v + 1];
    for (int base = beg; base < end; base += 128) {
        int j = base + tid;
        sS[tid] = (j < end) ? g_src[j] : 0;
        __syncthreads();
        int cnt = min(128, end - base);
        for (int jj = 0; jj < cnt; jj++) {
            const float* hjp = g_hj + sS[jj] * TH;
#pragma unroll
            for (int k = 0; k < 4; k++) {
                int c = tid + 128 * k;
                if (c < TH) {
                    float a = hjp[c];
                    sm[k] += a; sq[k] += a * a;
                    mn[k] = fminf(mn[k], a); mx[k] = fmaxf(mx[k], a);
                }
            }
        }
        __syncthreads();
    }
    int deg = end - beg;
    float* aggv = g_agg + v * 1600;
#pragma unroll
    for (int k = 0; k < 4; k++) {
        int c = tid + 128 * k;
        if (c >= TH) continue;
        int t = c / H, h = c % H;
        float cst = g_hi[v * TH + c] + preb[c];
        float mean_, mn_, mx_, std_;
        if (deg > 0) {
            float inv = 1.f / (float)deg;
            float Ab = sm[k] * inv;
            mean_ = cst + Ab;
            float var = sq[k] * inv - Ab * Ab;
            std_ = sqrtf(fmaxf(var, 0.f) + EPS_BN);
            mn_ = cst + mn[k];
            mx_ = cst + mx[k];
        } else {
            mean_ = 0.f; mn_ = 0.f; mx_ = 0.f; std_ = sqrtf(EPS_BN);
        }
        float* p = aggv + t * 320 + h;
        p[0] = mean_; p[80] = mn_; p[160] = mx_; p[240] = std_;
    }
}

// ---------------- GEMM 2: fused post-conv (virtual K=1040, per tower, N=16) ----------------
__global__ void k_gemm_post(const float* __restrict__ W, const float* __restrict__ b) {
    __shared__ __align__(16) float sX[16][128];
    __shared__ __align__(16) float sW[16][16];
    int tid = threadIdx.x;   // 128
    int t = blockIdx.y;
    int n0 = blockIdx.x * 128;
    int n = n0 + tid;
    bool nv = n < NN;
    float myAmp = nv ? g_amp[n] : 0.f;
    float myAtt = nv ? g_att[n] : 0.f;
    const float* Wt = W + t * 1040 * 16;
    float acc[4][4] = {};
    int nG = tid / 4, gG = tid % 4;
    for (int ck = 0; ck < 65; ck++) {
        int k0 = ck * 16;
        const float* ptr; float scale;
        if (k0 < 80)       { ptr = g_op  + n * H    + k0;              scale = 1.f;   }
        else if (k0 < 400) { ptr = g_agg + n * 1600 + t * 320 + (k0 - 80);  scale = 1.f;   }
        else if (k0 < 720) { ptr = g_agg + n * 1600 + t * 320 + (k0 - 400); scale = myAmp; }
        else               { ptr = g_agg + n * 1600 + t * 320 + (k0 - 720); scale = myAtt; }
#pragma unroll
        for (int q = 0; q < 4; q++) {
            float4 v = make_float4(0.f, 0.f, 0.f, 0.f);
            if (nv) v = *(const float4*)(ptr + q * 4);
            sX[q * 4 + 0][tid] = v.x * scale;
            sX[q * 4 + 1][tid] = v.y * scale;
            sX[q * 4 + 2][tid] = v.z * scale;
            sX[q * 4 + 3][tid] = v.w * scale;
        }
        if (tid < 64) {
            float4 wv = *(const float4*)(Wt + k0 * 16 + tid * 4);
            ((float4*)&sW[0][0])[tid] = wv;
        }
        __syncthreads();
#pragma unroll
        for (int k = 0; k < 16; k++) {
            float a[4], w[4];
            *(float4*)a = *(const float4*)&sX[k][nG * 4];
            *(float4*)w = *(const float4*)&sW[k][gG * 4];
#pragma unroll
            for (int i = 0; i < 4; i++)
#pragma unroll
                for (int j = 0; j < 4; j++) acc[i][j] += a[i] * w[j];
        }
        __syncthreads();
    }
#pragma unroll
    for (int i = 0; i < 4; i++) {
        int nn2 = n0 + nG * 4 + i;
        if (nn2 < NN) {
#pragma unroll
            for (int j = 0; j < 4; j++)
                g_c16[nn2 * H + t * 16 + gG * 4 + j] = acc[i][j] + b[t * 16 + gG * 4 + j];
        }
    }
}

// ---------------- GEMM 3: 80x80 linear ----------------
__global__ void k_gemm_lin(const float* __restrict__ W, const float* __restrict__ b) {
    __shared__ __align__(16) float sX[16][128];
    __shared__ __align__(16) float sW[16][16];
    int tid = threadIdx.x;   // 128
    int cb = blockIdx.y * 16;
    int n0 = blockIdx.x * 128;
    int n = n0 + tid;
    bool nv = n < NN;
    float acc[4][4] = {};
    int nG = tid / 4, gG = tid % 4;
    for (int ck = 0; ck < 5; ck++) {
        int k0 = ck * 16;
        const float* ptr = g_c16 + n * H + k0;
#pragma unroll
        for (int q = 0; q < 4; q++) {
            float4 v = make_float4(0.f, 0.f, 0.f, 0.f);
            if (nv) v = *(const float4*)(ptr + q * 4);
            sX[q * 4 + 0][tid] = v.x;
            sX[q * 4 + 1][tid] = v.y;
            sX[q * 4 + 2][tid] = v.z;
            sX[q * 4 + 3][tid] = v.w;
        }
        if (tid < 64) {
            int k = tid / 4, g = (tid % 4) * 4;
            float4 wv = *(const float4*)(W + (k0 + k) * H + cb + g);
            ((float4*)&sW[0][0])[tid] = wv;
        }
        __syncthreads();
#pragma unroll
        for (int k = 0; k < 16; k++) {
            float a[4], w[4];
            *(float4*)a = *(const float4*)&sX[k][nG * 4];
            *(float4*)w = *(const float4*)&sW[k][gG * 4];
#pragma unroll
            for (int i = 0; i < 4; i++)
#pragma unroll
                for (int j = 0; j < 4; j++) acc[i][j] += a[i] * w[j];
        }
        __syncthreads();
    }
#pragma unroll
    for (int i = 0; i < 4; i++) {
        int nn2 = n0 + nG * 4 + i;
        if (nn2 < NN) {
#pragma unroll
            for (int j = 0; j < 4; j++)
                g_lin[nn2 * H + cb + gG * 4 + j] = acc[i][j] + b[cb + gG * 4 + j];
        }
    }
}

// ---------------- BatchNorm ----------------
__global__ void k_bnstats() {   // one block per channel, deterministic tree reduce
    int c = blockIdx.x;
    int tid = threadIdx.x;   // 256
    float s = 0.f, q = 0.f;
    for (int n = tid; n < NN; n += 256) {
        float v = g_lin[n * H + c];
        s += v; q += v * v;
    }
    __shared__ float ss[256], sq[256];
    ss[tid] = s; sq[tid] = q; __syncthreads();
    for (int o = 128; o; o >>= 1) {
        if (tid < o) { ss[tid] += ss[tid + o]; sq[tid] += sq[tid + o]; }
        __syncthreads();
    }
    if (tid == 0) {
        float mu = ss[0] / (float)NN;
        float var = sq[0] / (float)NN - mu * mu;
        g_mu[c] = mu;
        g_rstd[c] = rsqrtf(fmaxf(var, 0.f) + EPS_BN);
    }
}

__global__ void k_bnapply(const float* __restrict__ gamma, const float* __restrict__ beta) {
    int i = blockIdx.x * blockDim.x + threadIdx.x;
    if (i < NN * H) {
        int h = i % H;
        float v = g_lin[i];
        v = gamma[h] * (v - g_mu[h]) * g_rstd[h] + beta[h];
        g_op[i] = fmaxf(v, 0.f);
    }
}

// ---------------- final head ----------------
__global__ void k_xc(const float* __restrict__ x) {
    int i = blockIdx.x * blockDim.x + threadIdx.x;
    if (i < NN * 40) {
        int n = i / 40, c = i % 40;
        float xc = g_op[n * H + c] * x[2 * n + 1] + g_op[n * H + 40 + c];
        g_logxc[i] = logf(xc + EPS_LOG);
    }
}

__global__ void k_logagg() {   // one warp per node
    int w = (blockIdx.x * blockDim.x + threadIdx.x) >> 5;
    int lane = threadIdx.x & 31;
    if (w >= NN) return;
    int beg = g_off[w], end = g_off[w + 1];
    float l0 = 0.f, l1 = 0.f;
    for (int e = beg; e < end; e++) {
        const float* lp = g_logxc + g_src[e] * 40;
        l0 += lp[lane];
        if (lane < 8) l1 += lp[lane + 32];
    }
    const float* lv = g_logxc + w * 40;
    g_xcf[w * 40 + lane] = expf(l0 + lv[lane]);
    if (lane < 8) g_xcf[w * 40 + lane + 32] = expf(l1 + lv[lane + 32]);
}

__global__ void k_pool(const int* __restrict__ batch) {
    const int NPB = 252;
    int tid = threadIdx.x;
    if (tid >= 240) return;
    int c = tid % 40, lane = tid / 40;
    int nend = min((int)(blockIdx.x + 1) * NPB, NN);
    float acc = 0.f, cacc = 0.f;
    int cur = -1;
    for (int n = blockIdx.x * NPB + lane; n < nend; n += 6) {
        int b = batch[n];
        if (b != cur) {
            if (cur >= 0) {
                atomicAdd(&g_gs[cur * 40 + c], acc);
                if (c == 0) atomicAdd(&g_gc[cur], cacc);
            }
            cur = b; acc = 0.f; cacc = 0.f;
        }
        acc += g_xcf[n * 40 + c];
        cacc += 1.f;
    }
    if (cur >= 0) {
        atomicAdd(&g_gs[cur * 40 + c], acc);
        if (c == 0) atomicAdd(&g_gc[cur], cacc);
    }
}

__global__ void k_final(const float* __restrict__ mlpW, const float* __restrict__ mlpb,
                        float* __restrict__ out) {
    int g = threadIdx.x;
    if (g < NGR) {
        float cnt = fmaxf(g_gc[g], 1.f);
        float acc = mlpb[0];
        for (int c = 0; c < 40; c++) acc += (g_gs[g * 40 + c] / cnt) * mlpW[c];
        out[g] = acc;
    }
}

// ---------------- launch ----------------
extern "C" void kernel_launch(void* const* d_in, const int* in_sizes, int n_in,
                              void* d_out, int out_size) {
    const float* x      = (const float*)d_in[0];
    const int*   ei     = (const int*)d_in[1];     // JAX default: int32!
    const int*   batch  = (const int*)d_in[2];     // int32
    const float* preW   = (const float*)d_in[3];
    const float* preB   = (const float*)d_in[4];
    const float* cpreW  = (const float*)d_in[5];
    const float* cpreB  = (const float*)d_in[6];
    const float* cpostW = (const float*)d_in[7];
    const float* cpostB = (const float*)d_in[8];
    const float* clinW  = (const float*)d_in[9];
    const float* clinB  = (const float*)d_in[10];
    const float* gamma  = (const float*)d_in[11];
    const float* beta   = (const float*)d_in[12];
    const float* mlpW   = (const float*)d_in[13];
    const float* mlpB   = (const float*)d_in[14];
    float* out = (float*)d_out;

    k_reset<<<32, 256>>>();
    k_count<<<(NE + 255) / 256, 256>>>(ei);
    k_scan<<<1, 1024>>>();
    k_scatter<<<(NE + 255) / 256, 256>>>(ei);
    k_delta<<<1, 1024>>>();
    k_nodeinfo<<<(NN + 255) / 256, 256>>>();
    k_op0<<<(NN * H + 255) / 256, 256>>>(x, preW, preB);

    for (int l = 0; l < 4; l++) {
        k_gemm_pre<<<dim3(125, 13), dim3(16, 16)>>>(cpreW + l * TW * 2 * H * H);
        k_agg<<<NN, 128>>>(cpreB + l * TW * H);
        k_gemm_post<<<dim3(63, TW), 128>>>(cpostW + l * TW * 13 * H * FO,
                                           cpostB + l * TW * FO);
        k_gemm_lin<<<dim3(63, 5), 128>>>(clinW + l * H * H, clinB + l * H);
        k_bnstats<<<H, 256>>>();
        k_bnapply<<<(NN * H + 255) / 256, 256>>>(gamma + l * H, beta + l * H);
    }

    k_xc<<<(NN * 40 + 255) / 256, 256>>>(x);
    k_logagg<<<1000, 256>>>();
    k_pool<<<32, 256>>>(batch);
    k_final<<<1, 32>>>(mlpW, mlpB, out);
}

// round 6
// speedup vs baseline: 1.0635x; 1.0635x over previous
#include <cuda_runtime.h>
#include <math.h>

#define NN 8000
#define NE 100000
#define NGR 16
#define H 80
#define TW 5
#define TH 400          // TW*H
#define FO 16
#define EPS_BN 1e-5f
#define EPS_LOG 1e-6f

// ---------------- scratch (device globals; no allocation allowed) ----------------
__device__ int   g_deg[NN];
__device__ int   g_fill[NN];
__device__ int   g_off[NN + 1];
__device__ int   g_src[NE];
__device__ float g_amp[NN];
__device__ float g_att[NN];
__device__ float g_delta;
__device__ __align__(16) float g_op[NN * H];
__device__ __align__(16) float g_hi[NN * TH];
__device__ __align__(16) float g_hj[NN * TH];
__device__ __align__(16) float g_agg[NN * 1600];   // [n][t*320 + stat*80 + h]
__device__ __align__(16) float g_P[NN * 240];      // [n][t*48 + grp*16 + j]
__device__ __align__(16) float g_c16[NN * H];
__device__ __align__(16) float g_lin[NN * H];
__device__ float g_mu[H];
__device__ float g_rstd[H];
__device__ float g_logxc[NN * 40];
__device__ float g_xcf[NN * 40];
__device__ float g_gs[NGR * 40];
__device__ float g_gc[NGR];

// ---------------- setup kernels ----------------
__global__ void k_reset() {
    int i = blockIdx.x * blockDim.x + threadIdx.x;
    if (i < NN) { g_deg[i] = 0; g_fill[i] = 0; }
    if (i < NGR * 40) g_gs[i] = 0.f;
    if (i < NGR) g_gc[i] = 0.f;
    if (i == 0) g_delta = 0.f;
}

__global__ void k_count(const int* __restrict__ ei) {
    int i = blockIdx.x * blockDim.x + threadIdx.x;
    if (i < NE) atomicAdd(&g_deg[ei[NE + i]], 1);
}

__global__ void k_scan() {   // single block, 1024 threads
    __shared__ int sh[1024];
    int tid = threadIdx.x;
    const int per = 8;
    int base = tid * per;
    int s = 0;
    for (int j = 0; j < per; j++) { int idx = base + j; if (idx < NN) s += g_deg[idx]; }
    sh[tid] = s; __syncthreads();
    for (int o = 1; o < 1024; o <<= 1) {
        int v = (tid >= o) ? sh[tid - o] : 0;
        __syncthreads();
        sh[tid] += v;
        __syncthreads();
    }
    int run = (tid == 0) ? 0 : sh[tid - 1];
    for (int j = 0; j < per; j++) {
        int idx = base + j;
        if (idx < NN) { g_off[idx] = run; run += g_deg[idx]; }
    }
    if (tid == 0) g_off[NN] = sh[1023];
}

__global__ void k_scatter(const int* __restrict__ ei) {
    int i = blockIdx.x * blockDim.x + threadIdx.x;
    if (i < NE) {
        int t = ei[NE + i];
        int p = g_off[t] + atomicAdd(&g_fill[t], 1);
        g_src[p] = ei[i];
    }
}

__global__ void k_delta() {  // single block
    __shared__ float sh[1024];
    int tid = threadIdx.x;
    float s = 0.f;
    for (int i = tid; i < NN; i += 1024) s += logf((float)g_deg[i] + 1.f);
    sh[tid] = s; __syncthreads();
    for (int o = 512; o; o >>= 1) { if (tid < o) sh[tid] += sh[tid + o]; __syncthreads(); }
    if (tid == 0) g_delta = sh[0] / (float)NN;
}

__global__ void k_nodeinfo() {
    int i = blockIdx.x * blockDim.x + threadIdx.x;
    if (i < NN) {
        int d = g_deg[i];
        float dc = (float)(d > 1 ? d : 1);
        float L = logf(dc + 1.f);
        float delta = g_delta;
        g_amp[i] = L / delta;
        g_att[i] = delta / L;
    }
}

__global__ void k_op0(const float* __restrict__ x, const float* __restrict__ W,
                      const float* __restrict__ b) {
    int i = blockIdx.x * blockDim.x + threadIdx.x;
    if (i < NN * H) {
        int n = i / H, h = i % H;
        g_op[i] = x[2 * n] * W[h] + b[h];
    }
}

// ---------------- GEMM 1: hi/hj = op @ conv_pre_W (M=8000, K=80, N=800) ----------------
__global__ void k_gemm_pre(const float* __restrict__ W) {   // W: (T, 2H, H) for this layer
    __shared__ __align__(16) float sA[16][64];
    __shared__ __align__(16) float sB[16][64];
    int tx = threadIdx.x, ty = threadIdx.y;
    int tid = ty * 16 + tx;
    int m0 = blockIdx.x * 64;
    int c0 = blockIdx.y * 64;
    float acc[4][4] = {};
    int nl = tid / 4, kq = tid % 4;   // A-staging role
    int cl = tid % 64, kq2 = tid / 64; // B-staging role
    for (int kk = 0; kk < 80; kk += 16) {
        float4 av = *(const float4*)(g_op + (m0 + nl) * H + kk + kq * 4);
        sA[kq * 4 + 0][nl] = av.x; sA[kq * 4 + 1][nl] = av.y;
        sA[kq * 4 + 2][nl] = av.z; sA[kq * 4 + 3][nl] = av.w;
#pragma unroll
        for (int j = 0; j < 4; j++) {
            int k = kq2 * 4 + j;
            int kg = kk + k;
            int c = c0 + cl;
            float val = 0.f;
            if (c < 800) {
                int cc = c < 400 ? c : c - 400;
                int f  = c < 400 ? kg : kg + 80;
                val = W[(cc / H * 160 + f) * H + (cc % H)];
            }
            sB[k][cl] = val;
        }
        __syncthreads();
#pragma unroll
        for (int k = 0; k < 16; k++) {
            float a[4], bv[4];
            *(float4*)a  = *(const float4*)&sA[k][ty * 4];
            *(float4*)bv = *(const float4*)&sB[k][tx * 4];
#pragma unroll
            for (int i = 0; i < 4; i++)
#pragma unroll
                for (int j = 0; j < 4; j++) acc[i][j] += a[i] * bv[j];
        }
        __syncthreads();
    }
#pragma unroll
    for (int i = 0; i < 4; i++) {
        int n = m0 + ty * 4 + i;
#pragma unroll
        for (int j = 0; j < 4; j++) {
            int c = c0 + tx * 4 + j;
            if (c < 800) {
                if (c < 400) g_hi[n * TH + c] = acc[i][j];
                else         g_hj[n * TH + c - 400] = acc[i][j];
            }
        }
    }
}

// ---------------- aggregation: per-node CSR gather of hj[src] ----------------
__global__ void k_agg(const float* __restrict__ preb) {  // preb: (T,H) for this layer
    int v = blockIdx.x;
    int tid = threadIdx.x;  // 128
    float sm[4] = {0, 0, 0, 0}, sq[4] = {0, 0, 0, 0};
    float mn[4], mx[4];
#pragma unroll
    for (int k = 0; k < 4; k++) { mn[k] = 3.4e38f; mx[k] = -3.4e38f; }
    __shared__ int sS[128];
    int beg = g_off[v], end = g_off[v + 1];
    for (int base = beg; base < end; base += 128) {
        int j = base + tid;
        sS[tid] = (j < end) ? g_src[j] : 0;
        __syncthreads();
        int cnt = min(128, end - base);
        for (int jj = 0; jj < cnt; jj++) {
            const float* hjp = g_hj + sS[jj] * TH;
#pragma unroll
            for (int k = 0; k < 4; k++) {
                int c = tid + 128 * k;
                if (c < TH) {
                    float a = hjp[c];
                    sm[k] += a; sq[k] += a * a;
                    mn[k] = fminf(mn[k], a); mx[k] = fmaxf(mx[k], a);
                }
            }
        }
        __syncthreads();
    }
    int deg = end - beg;
    float* aggv = g_agg + v * 1600;
#pragma unroll
    for (int k = 0; k < 4; k++) {
        int c = tid + 128 * k;
        if (c >= TH) continue;
        int t = c / H, h = c % H;
        float cst = g_hi[v * TH + c] + preb[c];
        float mean_, mn_, mx_, std_;
        if (deg > 0) {
            float inv = 1.f / (float)deg;
            float Ab = sm[k] * inv;
            mean_ = cst + Ab;
            float var = sq[k] * inv - Ab * Ab;
            std_ = sqrtf(fmaxf(var, 0.f) + EPS_BN);
            mn_ = cst + mn[k];
            mx_ = cst + mx[k];
        } else {
            mean_ = 0.f; mn_ = 0.f; mx_ = 0.f; std_ = sqrtf(EPS_BN);
        }
        float* p = aggv + t * 320 + h;
        p[0] = mean_; p[80] = mn_; p[160] = mx_; p[240] = std_;
    }
}

// ---------------- post80: c16 = op @ W0 + bias  (K=80, virtual N=80) ----------------
// Clone of k_gemm_lin; W0[k][t*16+j] = cpostW[(t*1040 + k)*16 + j]
__global__ void k_post80(const float* __restrict__ Wpost, const float* __restrict__ b) {
    __shared__ __align__(16) float sX[16][128];
    __shared__ __align__(16) float sW[16][16];
    int tid = threadIdx.x;   // 128
    int cb = blockIdx.y * 16;          // = t*16
    int t = blockIdx.y;
    int n0 = blockIdx.x * 128;
    int n = n0 + tid;
    bool nv = n < NN;
    float acc[4][4] = {};
    int nG = tid / 4, gG = tid % 4;
    for (int ck = 0; ck < 5; ck++) {
        int k0 = ck * 16;
        const float* ptr = g_op + n * H + k0;
#pragma unroll
        for (int q = 0; q < 4; q++) {
            float4 v = make_float4(0.f, 0.f, 0.f, 0.f);
            if (nv) v = *(const float4*)(ptr + q * 4);
            sX[q * 4 + 0][tid] = v.x;
            sX[q * 4 + 1][tid] = v.y;
            sX[q * 4 + 2][tid] = v.z;
            sX[q * 4 + 3][tid] = v.w;
        }
        if (tid < 64) {
            int k = tid / 4, g = (tid % 4) * 4;
            float4 wv = *(const float4*)(Wpost + (t * 1040 + k0 + k) * 16 + g);
            ((float4*)&sW[0][0])[tid] = wv;
        }
        __syncthreads();
#pragma unroll
        for (int k = 0; k < 16; k++) {
            float a[4], w[4];
            *(float4*)a = *(const float4*)&sX[k][nG * 4];
            *(float4*)w = *(const float4*)&sW[k][gG * 4];
#pragma unroll
            for (int i = 0; i < 4; i++)
#pragma unroll
                for (int j = 0; j < 4; j++) acc[i][j] += a[i] * w[j];
        }
        __syncthreads();
    }
#pragma unroll
    for (int i = 0; i < 4; i++) {
        int nn2 = n0 + nG * 4 + i;
        if (nn2 < NN) {
#pragma unroll
            for (int j = 0; j < 4; j++)
                g_c16[nn2 * H + cb + gG * 4 + j] = acc[i][j] + b[cb + gG * 4 + j];
        }
    }
}

// ---------------- gemm_P: P[n][t*48+grp*16+j] = agg_t @ W_grp  (K=320, N=16) ----------------
// Clone of k_gemm_lin with K=320; blockIdx.y encodes (t, grp), t=y/3, grp=y%3.
__global__ void k_gemm_P(const float* __restrict__ Wpost) {
    __shared__ __align__(16) float sX[16][128];
    __shared__ __align__(16) float sW[16][16];
    int tid = threadIdx.x;   // 128
    int t = blockIdx.y / 3, grp = blockIdx.y % 3;
    int n0 = blockIdx.x * 128;
    int n = n0 + tid;
    bool nv = n < NN;
    float acc[4][4] = {};
    int nG = tid / 4, gG = tid % 4;
    int wrow0 = t * 1040 + 80 + grp * 320;
    for (int ck = 0; ck < 20; ck++) {
        int k0 = ck * 16;
        const float* ptr = g_agg + n * 1600 + t * 320 + k0;
#pragma unroll
        for (int q = 0; q < 4; q++) {
            float4 v = make_float4(0.f, 0.f, 0.f, 0.f);
            if (nv) v = *(const float4*)(ptr + q * 4);
            sX[q * 4 + 0][tid] = v.x;
            sX[q * 4 + 1][tid] = v.y;
            sX[q * 4 + 2][tid] = v.z;
            sX[q * 4 + 3][tid] = v.w;
        }
        if (tid < 64) {
            int k = tid / 4, g = (tid % 4) * 4;
            float4 wv = *(const float4*)(Wpost + (wrow0 + k0 + k) * 16 + g);
            ((float4*)&sW[0][0])[tid] = wv;
        }
        __syncthreads();
#pragma unroll
        for (int k = 0; k < 16; k++) {
            float a[4], w[4];
            *(float4*)a = *(const float4*)&sX[k][nG * 4];
            *(float4*)w = *(const float4*)&sW[k][gG * 4];
#pragma unroll
            for (int i = 0; i < 4; i++)
#pragma unroll
                for (int j = 0; j < 4; j++) acc[i][j] += a[i] * w[j];
        }
        __syncthreads();
    }
#pragma unroll
    for (int i = 0; i < 4; i++) {
        int nn2 = n0 + nG * 4 + i;
        if (nn2 < NN) {
#pragma unroll
            for (int j = 0; j < 4; j++)
                g_P[nn2 * 240 + t * 48 + grp * 16 + gG * 4 + j] = acc[i][j];
        }
    }
}

// ---------------- combine: c16 += P1 + amp*P2 + att*P3 ----------------
__global__ void k_combine() {
    int i = blockIdx.x * blockDim.x + threadIdx.x;
    if (i < NN * H) {
        int n = i / H, c = i % H;
        int t = c / 16, j = c % 16;
        const float* p = g_P + n * 240 + t * 48 + j;
        g_c16[i] += p[0] + g_amp[n] * p[16] + g_att[n] * p[32];
    }
}

// ---------------- GEMM 3: 80x80 linear ----------------
__global__ void k_gemm_lin(const float* __restrict__ W, const float* __restrict__ b) {
    __shared__ __align__(16) float sX[16][128];
    __shared__ __align__(16) float sW[16][16];
    int tid = threadIdx.x;   // 128
    int cb = blockIdx.y * 16;
    int n0 = blockIdx.x * 128;
    int n = n0 + tid;
    bool nv = n < NN;
    float acc[4][4] = {};
    int nG = tid / 4, gG = tid % 4;
    for (int ck = 0; ck < 5; ck++) {
        int k0 = ck * 16;
        const float* ptr = g_c16 + n * H + k0;
#pragma unroll
        for (int q = 0; q < 4; q++) {
            float4 v = make_float4(0.f, 0.f, 0.f, 0.f);
            if (nv) v = *(const float4*)(ptr + q * 4);
            sX[q * 4 + 0][tid] = v.x;
            sX[q * 4 + 1][tid] = v.y;
            sX[q * 4 + 2][tid] = v.z;
            sX[q * 4 + 3][tid] = v.w;
        }
        if (tid < 64) {
            int k = tid / 4, g = (tid % 4) * 4;
            float4 wv = *(const float4*)(W + (k0 + k) * H + cb + g);
            ((float4*)&sW[0][0])[tid] = wv;
        }
        __syncthreads();
#pragma unroll
        for (int k = 0; k < 16; k++) {
            float a[4], w[4];
            *(float4*)a = *(const float4*)&sX[k][nG * 4];
            *(float4*)w = *(const float4*)&sW[k][gG * 4];
#pragma unroll
            for (int i = 0; i < 4; i++)
#pragma unroll
                for (int j = 0; j < 4; j++) acc[i][j] += a[i] * w[j];
        }
        __syncthreads();
    }
#pragma unroll
    for (int i = 0; i < 4; i++) {
        int nn2 = n0 + nG * 4 + i;
        if (nn2 < NN) {
#pragma unroll
            for (int j = 0; j < 4; j++)
                g_lin[nn2 * H + cb + gG * 4 + j] = acc[i][j] + b[cb + gG * 4 + j];
        }
    }
}

// ---------------- BatchNorm ----------------
__global__ void k_bnstats() {   // one block per channel, deterministic tree reduce
    int c = blockIdx.x;
    int tid = threadIdx.x;   // 256
    float s = 0.f, q = 0.f;
    for (int n = tid; n < NN; n += 256) {
        float v = g_lin[n * H + c];
        s += v; q += v * v;
    }
    __shared__ float ss[256], sq[256];
    ss[tid] = s; sq[tid] = q; __syncthreads();
    for (int o = 128; o; o >>= 1) {
        if (tid < o) { ss[tid] += ss[tid + o]; sq[tid] += sq[tid + o]; }
        __syncthreads();
    }
    if (tid == 0) {
        float mu = ss[0] / (float)NN;
        float var = sq[0] / (float)NN - mu * mu;
        g_mu[c] = mu;
        g_rstd[c] = rsqrtf(fmaxf(var, 0.f) + EPS_BN);
    }
}

__global__ void k_bnapply(const float* __restrict__ gamma, const float* __restrict__ beta) {
    int i = blockIdx.x * blockDim.x + threadIdx.x;
    if (i < NN * H) {
        int h = i % H;
        float v = g_lin[i];
        v = gamma[h] * (v - g_mu[h]) * g_rstd[h] + beta[h];
        g_op[i] = fmaxf(v, 0.f);
    }
}

// ---------------- final head ----------------
__global__ void k_xc(const float* __restrict__ x) {
    int i = blockIdx.x * blockDim.x + threadIdx.x;
    if (i < NN * 40) {
        int n = i / 40, c = i % 40;
        float xc = g_op[n * H + c] * x[2 * n + 1] + g_op[n * H + 40 + c];
        g_logxc[i] = logf(xc + EPS_LOG);
    }
}

__global__ void k_logagg() {   // one warp per node
    int w = (blockIdx.x * blockDim.x + threadIdx.x) >> 5;
    int lane = threadIdx.x & 31;
    if (w >= NN) return;
    int beg = g_off[w], end = g_off[w + 1];
    float l0 = 0.f, l1 = 0.f;
    for (int e = beg; e < end; e++) {
        const float* lp = g_logxc + g_src[e] * 40;
        l0 += lp[lane];
        if (lane < 8) l1 += lp[lane + 32];
    }
    const float* lv = g_logxc + w * 40;
    g_xcf[w * 40 + lane] = expf(l0 + lv[lane]);
    if (lane < 8) g_xcf[w * 40 + lane + 32] = expf(l1 + lv[lane + 32]);
}

__global__ void k_pool(const int* __restrict__ batch) {
    const int NPB = 252;
    int tid = threadIdx.x;
    if (tid >= 240) return;
    int c = tid % 40, lane = tid / 40;
    int nend = min((int)(blockIdx.x + 1) * NPB, NN);
    float acc = 0.f, cacc = 0.f;
    int cur = -1;
    for (int n = blockIdx.x * NPB + lane; n < nend; n += 6) {
        int b = batch[n];
        if (b != cur) {
            if (cur >= 0) {
                atomicAdd(&g_gs[cur * 40 + c], acc);
                if (c == 0) atomicAdd(&g_gc[cur], cacc);
            }
            cur = b; acc = 0.f; cacc = 0.f;
        }
        acc += g_xcf[n * 40 + c];
        cacc += 1.f;
    }
    if (cur >= 0) {
        atomicAdd(&g_gs[cur * 40 + c], acc);
        if (c == 0) atomicAdd(&g_gc[cur], cacc);
    }
}

__global__ void k_final(const float* __restrict__ mlpW, const float* __restrict__ mlpb,
                        float* __restrict__ out) {
    int g = threadIdx.x;
    if (g < NGR) {
        float cnt = fmaxf(g_gc[g], 1.f);
        float acc = mlpb[0];
        for (int c = 0; c < 40; c++) acc += (g_gs[g * 40 + c] / cnt) * mlpW[c];
        out[g] = acc;
    }
}

// ---------------- launch ----------------
extern "C" void kernel_launch(void* const* d_in, const int* in_sizes, int n_in,
                              void* d_out, int out_size) {
    const float* x      = (const float*)d_in[0];
    const int*   ei     = (const int*)d_in[1];     // JAX default int32
    const int*   batch  = (const int*)d_in[2];
    const float* preW   = (const float*)d_in[3];
    const float* preB   = (const float*)d_in[4];
    const float* cpreW  = (const float*)d_in[5];
    const float* cpreB  = (const float*)d_in[6];
    const float* cpostW = (const float*)d_in[7];
    const float* cpostB = (const float*)d_in[8];
    const float* clinW  = (const float*)d_in[9];
    const float* clinB  = (const float*)d_in[10];
    const float* gamma  = (const float*)d_in[11];
    const float* beta   = (const float*)d_in[12];
    const float* mlpW   = (const float*)d_in[13];
    const float* mlpB   = (const float*)d_in[14];
    float* out = (float*)d_out;

    k_reset<<<32, 256>>>();
    k_count<<<(NE + 255) / 256, 256>>>(ei);
    k_scan<<<1, 1024>>>();
    k_scatter<<<(NE + 255) / 256, 256>>>(ei);
    k_delta<<<1, 1024>>>();
    k_nodeinfo<<<(NN + 255) / 256, 256>>>();
    k_op0<<<(NN * H + 255) / 256, 256>>>(x, preW, preB);

    for (int l = 0; l < 4; l++) {
        k_gemm_pre<<<dim3(125, 13), dim3(16, 16)>>>(cpreW + l * TW * 2 * H * H);
        k_agg<<<NN, 128>>>(cpreB + l * TW * H);
        k_post80<<<dim3(63, 5), 128>>>(cpostW + l * TW * 13 * H * FO, cpostB + l * TW * FO);
        k_gemm_P<<<dim3(63, 15), 128>>>(cpostW + l * TW * 13 * H * FO);
        k_combine<<<(NN * H + 255) / 256, 256>>>();
        k_gemm_lin<<<dim3(63, 5), 128>>>(clinW + l * H * H, clinB + l * H);
        k_bnstats<<<H, 256>>>();
        k_bnapply<<<(NN * H + 255) / 256, 256>>>(gamma + l * H, beta + l * H);
    }

    k_xc<<<(NN * 40 + 255) / 256, 256>>>(x);
    k_logagg<<<1000, 256>>>();
    k_pool<<<32, 256>>>(batch);
    k_final<<<1, 32>>>(mlpW, mlpB, out);
}